// round 8
// baseline (speedup 1.0000x reference)
#include <cuda_runtime.h>
#include <cuda_bf16.h>

#define N_NODES 100000
#define F_IN 256
#define F_OUT 16

typedef unsigned long long ull;

// Scratch (static __device__ — no allocation allowed). All zero-init at load;
// g_deg is re-zeroed by k_final each run (self-loop folded as deg+1).
__device__ __align__(16) float g_deg[N_NODES];
__device__ __align__(16) float g_hn1[N_NODES * F_OUT];   // raw then scaled messages
__device__ __align__(16) float g_agg1[N_NODES * F_OUT];  // fp32 accum, init = self-loop
__device__ __align__(16) float g_hn2[N_NODES];
__device__ __align__(16) float g_agg2[N_NODES];

#define FFMA2(d, a, b) asm("fma.rn.f32x2 %0, %1, %2, %0;" : "+l"(d) : "l"(a), "l"(b))
#define REDV4(p, v) asm volatile("red.global.add.v4.f32 [%0], {%1, %2, %3, %4};" \
    :: "l"(p), "f"((v).x), "f"((v).y), "f"((v).z), "f"((v).w) : "memory")

// ---------------------------------------------------------------------------
// K1 (fused): blocks [0, nbGemm) = GEMM1 raw (hn1 = x@W1, unscaled);
//             blocks [nbGemm, ..) = degree atomics (independent of GEMM).
// 8 nodes x 4 f per thread, f32x2 packed accumulators.
// Conflict-free smem: gap-4 column layout col(n)=n+(n>>3)*4 (16B-aligned
// 8-node groups -> x via 2x LDS.128 @ 1 cyc) + k-dependent shift s=4*(k>>2)
// making the transposed STS conflict-free.
#define KC 16
#define XSTR 780            // row stride (floats); max col 763 + max shift 12 < 780
#define NPB 512
#define GEMM_SMEM (KC * XSTR * 4 + F_IN * F_OUT * 8)

__global__ __launch_bounds__(256, 2) void k_fused(const float* __restrict__ x,
                                                  const float* __restrict__ W1,
                                                  const int* __restrict__ dst,
                                                  int E, int nbGemm) {
    extern __shared__ float smem[];
    int tid = threadIdx.x;

    if (blockIdx.x >= nbGemm) {
        // ---- degree pass: 4 edges/thread via int4, tail on thread E4 ----
        int E4 = E >> 2;
        int t = (blockIdx.x - nbGemm) * 256 + tid;
        if (t < E4) {
            int4 d = __ldg((const int4*)dst + t);
            atomicAdd(&g_deg[d.x], 1.0f);
            atomicAdd(&g_deg[d.y], 1.0f);
            atomicAdd(&g_deg[d.z], 1.0f);
            atomicAdd(&g_deg[d.w], 1.0f);
        } else if (t == E4) {
            for (int e = E4 * 4; e < E; e++) atomicAdd(&g_deg[dst[e]], 1.0f);
        }
        return;
    }

    // ---- GEMM1 raw ----
    float*  sX  = smem;                          // [KC][XSTR], swizzled columns
    float2* sWd = (float2*)(smem + KC * XSTR);   // [F_IN][F_OUT] duplicated pairs

    int n0 = blockIdx.x * NPB;
    for (int i = tid; i < F_IN * F_OUT; i += 256) {
        float w = W1[i];
        sWd[i] = make_float2(w, w);
    }

    int nq = tid >> 2;      // 0..63 -> nodes nq*8 .. nq*8+7
    int fq = tid & 3;       // 0..3

    ull acc[4][4];          // [f][node-pair]
    #pragma unroll
    for (int f = 0; f < 4; f++)
        #pragma unroll
        for (int p = 0; p < 4; p++) acc[f][p] = 0ull;

    for (int kc = 0; kc < F_IN; kc += KC) {
        __syncthreads();
        // stage x chunk transposed+swizzled: 512 nodes x 16 k
        #pragma unroll
        for (int j = 0; j < (NPB * KC / 4) / 256; j++) {   // 8 iters
            int i = tid + j * 256;
            int n = i >> 2;          // 0..511
            int kq = i & 3;          // k = kq*4 + c
            int row = n0 + n; if (row >= N_NODES) row = N_NODES - 1;
            float4 v = __ldg((const float4*)(x + (size_t)row * F_IN + kc) + kq);
            int col = n + ((n >> 3) << 2) + (kq << 2);     // gap-4 + shift s=4*kq
            sX[(kq * 4 + 0) * XSTR + col] = v.x;
            sX[(kq * 4 + 1) * XSTR + col] = v.y;
            sX[(kq * 4 + 2) * XSTR + col] = v.z;
            sX[(kq * 4 + 3) * XSTR + col] = v.w;
        }
        __syncthreads();
        #pragma unroll
        for (int k = 0; k < KC; k++) {
            int shift = (k >> 2) << 2;                     // s = 4*(k>>2)
            const float* xp = sX + k * XSTR + nq * 12 + shift;
            ulonglong2 xA = *(const ulonglong2*)xp;        // nodes 0-3 (2 pairs)
            ulonglong2 xB = *(const ulonglong2*)(xp + 4);  // nodes 4-7
            const ulonglong2* wp = (const ulonglong2*)(sWd + (kc + k) * F_OUT + fq * 4);
            ulonglong2 w01 = wp[0];
            ulonglong2 w23 = wp[1];
            FFMA2(acc[0][0], xA.x, w01.x); FFMA2(acc[0][1], xA.y, w01.x);
            FFMA2(acc[0][2], xB.x, w01.x); FFMA2(acc[0][3], xB.y, w01.x);
            FFMA2(acc[1][0], xA.x, w01.y); FFMA2(acc[1][1], xA.y, w01.y);
            FFMA2(acc[1][2], xB.x, w01.y); FFMA2(acc[1][3], xB.y, w01.y);
            FFMA2(acc[2][0], xA.x, w23.x); FFMA2(acc[2][1], xA.y, w23.x);
            FFMA2(acc[2][2], xB.x, w23.x); FFMA2(acc[2][3], xB.y, w23.x);
            FFMA2(acc[3][0], xA.x, w23.y); FFMA2(acc[3][1], xA.y, w23.y);
            FFMA2(acc[3][2], xB.x, w23.y); FFMA2(acc[3][3], xB.y, w23.y);
        }
    }

    #pragma unroll
    for (int j = 0; j < 8; j++) {
        int node = n0 + nq * 8 + j;
        if (node >= N_NODES) break;
        int p = j >> 1, hi = j & 1;
        union { ull u; float2 f; } c0, c1, c2, c3;
        c0.u = acc[0][p]; c1.u = acc[1][p]; c2.u = acc[2][p]; c3.u = acc[3][p];
        float4 o;
        o.x = hi ? c0.f.y : c0.f.x;
        o.y = hi ? c1.f.y : c1.f.x;
        o.z = hi ? c2.f.y : c2.f.x;
        o.w = hi ? c3.f.y : c3.f.x;
        *((float4*)(g_hn1 + (size_t)node * F_OUT) + fq) = o;   // raw, unscaled
    }
}

// ---------------------------------------------------------------------------
// K2: scale: hn1 *= isq (messages), agg1 = hn1*isq (self-loop init)
__global__ void k_scale() {
    int t = blockIdx.x * blockDim.x + threadIdx.x;
    int n = t >> 2;
    int fq = t & 3;
    if (n >= N_NODES) return;
    float isq = rsqrtf(g_deg[n] + 1.0f);
    float4* hp = (float4*)(g_hn1 + (size_t)n * F_OUT) + fq;
    float4 o = *hp;
    o.x *= isq; o.y *= isq; o.z *= isq; o.w *= isq;
    *hp = o;
    *((float4*)(g_agg1 + (size_t)n * F_OUT) + fq) = o;
}

// ---------------------------------------------------------------------------
// K3: edge aggregation layer 1: agg1[dst] += hn1[src]
// 4 lanes per edge, 4 independent edge-chains per thread (E % 4 == 0 path).
__global__ void k_edge1_v4(const int* __restrict__ src, const int* __restrict__ dst,
                           int Eq) {
    int t = blockIdx.x * blockDim.x + threadIdx.x;
    int q = t >> 2;
    int c = t & 3;
    if (q >= Eq) return;
    int e0 = q, e1 = q + Eq, e2 = q + 2 * Eq, e3 = q + 3 * Eq;
    int s0 = __ldg(src + e0), d0 = __ldg(dst + e0);
    int s1 = __ldg(src + e1), d1 = __ldg(dst + e1);
    int s2 = __ldg(src + e2), d2 = __ldg(dst + e2);
    int s3 = __ldg(src + e3), d3 = __ldg(dst + e3);
    float4 v0 = __ldg((const float4*)(g_hn1 + (size_t)s0 * F_OUT) + c);
    float4 v1 = __ldg((const float4*)(g_hn1 + (size_t)s1 * F_OUT) + c);
    float4 v2 = __ldg((const float4*)(g_hn1 + (size_t)s2 * F_OUT) + c);
    float4 v3 = __ldg((const float4*)(g_hn1 + (size_t)s3 * F_OUT) + c);
    REDV4(g_agg1 + (size_t)d0 * F_OUT + c * 4, v0);
    REDV4(g_agg1 + (size_t)d1 * F_OUT + c * 4, v1);
    REDV4(g_agg1 + (size_t)d2 * F_OUT + c * 4, v2);
    REDV4(g_agg1 + (size_t)d3 * F_OUT + c * 4, v3);
}
// fallback: 1 edge per 4 lanes
__global__ void k_edge1_s(const int* __restrict__ src, const int* __restrict__ dst,
                          int E) {
    int t = blockIdx.x * blockDim.x + threadIdx.x;
    int e = t >> 2;
    int c = t & 3;
    if (e >= E) return;
    int s = __ldg(src + e);
    int d = __ldg(dst + e);
    float4 v = __ldg((const float4*)(g_hn1 + (size_t)s * F_OUT) + c);
    REDV4(g_agg1 + (size_t)d * F_OUT + c * 4, v);
}

// ---------------------------------------------------------------------------
// K4: node epilogue L1 + GEMM2 (16->1) + fold scale
__global__ void k_node2(const float* __restrict__ b1, const float* __restrict__ W2) {
    int n = blockIdx.x * blockDim.x + threadIdx.x;
    if (n >= N_NODES) return;
    float isq = rsqrtf(g_deg[n] + 1.0f);
    const float4* ar = (const float4*)(g_agg1 + (size_t)n * F_OUT);
    float h2 = 0.0f;
    #pragma unroll
    for (int c = 0; c < 4; c++) {
        float4 a = ar[c];
        float v;
        v = fmaxf(fmaf(isq, a.x, __ldg(b1 + c * 4 + 0)), 0.0f); h2 = fmaf(v, __ldg(W2 + c * 4 + 0), h2);
        v = fmaxf(fmaf(isq, a.y, __ldg(b1 + c * 4 + 1)), 0.0f); h2 = fmaf(v, __ldg(W2 + c * 4 + 1), h2);
        v = fmaxf(fmaf(isq, a.z, __ldg(b1 + c * 4 + 2)), 0.0f); h2 = fmaf(v, __ldg(W2 + c * 4 + 2), h2);
        v = fmaxf(fmaf(isq, a.w, __ldg(b1 + c * 4 + 3)), 0.0f); h2 = fmaf(v, __ldg(W2 + c * 4 + 3), h2);
    }
    float v2 = h2 * isq;
    g_hn2[n] = v2;
    g_agg2[n] = v2;                  // self-loop init
}

// ---------------------------------------------------------------------------
// K5: edge aggregation layer 2 (scalar), 8 edges/thread (2x int4) + tail
__global__ void k_edge2(const int* __restrict__ src, const int* __restrict__ dst,
                        int E) {
    int E8 = E >> 3;
    int t = blockIdx.x * blockDim.x + threadIdx.x;
    if (t < E8) {
        int4 sa = __ldg((const int4*)src + 2 * t);
        int4 sb = __ldg((const int4*)src + 2 * t + 1);
        int4 da = __ldg((const int4*)dst + 2 * t);
        int4 db = __ldg((const int4*)dst + 2 * t + 1);
        float ha = __ldg(g_hn2 + sa.x), hb = __ldg(g_hn2 + sa.y);
        float hc = __ldg(g_hn2 + sa.z), hd = __ldg(g_hn2 + sa.w);
        float he = __ldg(g_hn2 + sb.x), hf = __ldg(g_hn2 + sb.y);
        float hg = __ldg(g_hn2 + sb.z), hh = __ldg(g_hn2 + sb.w);
        atomicAdd(&g_agg2[da.x], ha);
        atomicAdd(&g_agg2[da.y], hb);
        atomicAdd(&g_agg2[da.z], hc);
        atomicAdd(&g_agg2[da.w], hd);
        atomicAdd(&g_agg2[db.x], he);
        atomicAdd(&g_agg2[db.y], hf);
        atomicAdd(&g_agg2[db.z], hg);
        atomicAdd(&g_agg2[db.w], hh);
    } else if (t == E8) {
        for (int e = E8 * 8; e < E; e++)
            atomicAdd(&g_agg2[dst[e]], g_hn2[src[e]]);
    }
}

// K6: final output; also re-zeros g_deg for the next (graph-replayed) run.
__global__ void k_final(float* __restrict__ out, const float* __restrict__ b2) {
    int n = blockIdx.x * blockDim.x + threadIdx.x;
    if (n >= N_NODES) return;
    float d = g_deg[n];
    out[n] = fmaf(rsqrtf(d + 1.0f), g_agg2[n], __ldg(b2));
    g_deg[n] = 0.0f;
}

// ---------------------------------------------------------------------------
extern "C" void kernel_launch(void* const* d_in, const int* in_sizes, int n_in,
                              void* d_out, int out_size) {
    const float* x  = (const float*)d_in[0];
    const int*   ei = (const int*)d_in[1];
    const float* W1 = (const float*)d_in[2];
    const float* b1 = (const float*)d_in[3];
    const float* W2 = (const float*)d_in[4];
    const float* b2 = (const float*)d_in[5];
    float* out = (float*)d_out;

    int E = in_sizes[1] / 2;
    const int* src = ei;
    const int* dst = ei + E;

    int nb_nodes = (N_NODES + 255) / 256;
    int nb_gemm  = (N_NODES + NPB - 1) / NPB;
    int nb_deg   = ((E >> 2) + 1 + 255) / 256;
    int nb_e2    = ((E >> 3) + 1 + 255) / 256;
    int nb_scale = (N_NODES * 4 + 255) / 256;

    cudaFuncSetAttribute(k_fused, cudaFuncAttributeMaxDynamicSharedMemorySize,
                         GEMM_SMEM);

    k_fused<<<nb_gemm + nb_deg, 256, GEMM_SMEM>>>(x, W1, dst, E, nb_gemm);
    k_scale<<<nb_scale, 256>>>();
    if ((E & 3) == 0) {
        int Eq = E >> 2;
        int nb_e1 = ((Eq * 4) + 255) / 256;
        k_edge1_v4<<<nb_e1, 256>>>(src, dst, Eq);
    } else {
        int nb_e1 = ((E * 4) + 255) / 256;
        k_edge1_s<<<nb_e1, 256>>>(src, dst, E);
    }
    k_node2<<<nb_nodes, 256>>>(b1, W2);
    k_edge2<<<nb_e2, 256>>>(src, dst, E);
    k_final<<<nb_nodes, 256>>>(out, b2);
}